// round 7
// baseline (speedup 1.0000x reference)
#include <cuda_runtime.h>
#include <math.h>

// Problem dims
#define CB   64      // batch
#define CL   40      // seq len
#define CT   39      // decoder steps (L-1)
#define CH   512     // hidden
#define CDF  2048    // feature dim
#define CE   512     // embedding dim
#define CV   20000   // vocab
#define G4   2048    // 4*H

typedef unsigned long long u64;

// ---------------- scratch (single __device__ global, no allocation) ----------------
constexpr int OFF_X    = 0;
constexpr int OFF_GINF = OFF_X    + CB*CL*CH;     // 1,310,720
constexpr int OFF_GINB = OFF_GINF + CB*CL*G4;     // +5,242,880
constexpr int OFF_HF   = OFF_GINB + CB*CL*G4;
constexpr int OFF_HB   = OFF_HF   + CL*CB*CH;
constexpr int OFF_HD   = OFF_HB   + CL*CB*CH;     // hD layout [B][T][H]
constexpr int OFF_CF   = OFF_HD   + CB*CT*CH;
constexpr int OFF_CB2  = OFF_CF   + CB*CH;
constexpr int OFF_CD   = OFF_CB2  + CB*CH;
constexpr int OFF_HZ   = OFF_CD   + CB*CH;
constexpr int OFF_CTX  = OFF_HZ   + CB*CH;
constexpr int OFF_DEMB = OFF_CTX  + CB*2*CH;
constexpr int OFF_EMBW = OFF_DEMB + CT*CB*CE;
constexpr int OFF_CTXW = OFF_EMBW + CT*CB*G4;
constexpr int OFF_PART = OFF_CTXW + CB*G4;
constexpr int SCRATCH_TOTAL = OFF_PART + 4*CB*G4; // 22,937,600 floats (~92 MB)

__device__ float g_scratch[SCRATCH_TOTAL];

// ---------------- helpers ----------------
__device__ __forceinline__ void fma2(u64 &d, u64 a, u64 b) {
    asm("fma.rn.f32x2 %0, %1, %2, %0;" : "+l"(d) : "l"(a), "l"(b));
}
__device__ __forceinline__ float pairsum(u64 v) {
    float lo = __uint_as_float((unsigned)(v & 0xffffffffull));
    float hi = __uint_as_float((unsigned)(v >> 32));
    return lo + hi;
}
// store a float4 into pad-2 smem (rows are 8B-aligned, not 16B) via two 8B stores
__device__ __forceinline__ void sts4(float* dst, float4 v) {
    *reinterpret_cast<float2*>(dst)     = make_float2(v.x, v.y);
    *reinterpret_cast<float2*>(dst + 2) = make_float2(v.z, v.w);
}

// ---------------- big GEMM: C[M,N] = A[M,K] * W[N,K]^T (+bias0 +bias1) ----------------
// BM=64, BN=128, BK=32; 256 threads; thread tile 4x8; f32x2 packed along K.
__global__ __launch_bounds__(256) void gemm_big(
    const float* __restrict__ A, int lda,
    const float* __restrict__ W, int ldw,
    float* __restrict__ C, int ldc,
    int M, int N, int K,
    const float* __restrict__ bias0,
    const float* __restrict__ bias1)
{
    __shared__ float As[64][34];
    __shared__ float Ws[128][34];
    const int tid  = threadIdx.x;
    const int m0   = blockIdx.x * 64;
    const int n0   = blockIdx.y * 128;
    const int tm   = tid >> 4;          // 0..15
    const int tn   = tid & 15;          // 0..15
    const int lrow = tid >> 3;          // 0..31
    const int lcol = (tid & 7) << 2;    // 0..28

    u64 acc[4][8];
#pragma unroll
    for (int i = 0; i < 4; i++)
#pragma unroll
        for (int j = 0; j < 8; j++) acc[i][j] = 0ull;

    const int nk = K >> 5;
    float4 pa[2], pw[4];
    const float4 z4 = make_float4(0.f, 0.f, 0.f, 0.f);
    {   // prefetch chunk 0
        int k  = lcol;
        int r0 = m0 + lrow, r1 = r0 + 32;
        pa[0] = (r0 < M) ? *reinterpret_cast<const float4*>(A + (long)r0 * lda + k) : z4;
        pa[1] = (r1 < M) ? *reinterpret_cast<const float4*>(A + (long)r1 * lda + k) : z4;
#pragma unroll
        for (int q = 0; q < 4; q++) {
            int rw = n0 + lrow + 32 * q;
            pw[q] = (rw < N) ? *reinterpret_cast<const float4*>(W + (long)rw * ldw + k) : z4;
        }
    }

    for (int c = 0; c < nk; c++) {
        sts4(&As[lrow][lcol],        pa[0]);
        sts4(&As[lrow + 32][lcol],   pa[1]);
#pragma unroll
        for (int q = 0; q < 4; q++) sts4(&Ws[lrow + 32 * q][lcol], pw[q]);
        __syncthreads();

        if (c + 1 < nk) {
            int k  = ((c + 1) << 5) + lcol;
            int r0 = m0 + lrow, r1 = r0 + 32;
            pa[0] = (r0 < M) ? *reinterpret_cast<const float4*>(A + (long)r0 * lda + k) : z4;
            pa[1] = (r1 < M) ? *reinterpret_cast<const float4*>(A + (long)r1 * lda + k) : z4;
#pragma unroll
            for (int q = 0; q < 4; q++) {
                int rw = n0 + lrow + 32 * q;
                pw[q] = (rw < N) ? *reinterpret_cast<const float4*>(W + (long)rw * ldw + k) : z4;
            }
        }

#pragma unroll
        for (int kk = 0; kk < 16; kk++) {
            u64 a2[4], w2[8];
#pragma unroll
            for (int i = 0; i < 4; i++)
                a2[i] = *reinterpret_cast<const u64*>(&As[tm + 16 * i][kk << 1]);
#pragma unroll
            for (int j = 0; j < 8; j++)
                w2[j] = *reinterpret_cast<const u64*>(&Ws[tn + 16 * j][kk << 1]);
#pragma unroll
            for (int i = 0; i < 4; i++)
#pragma unroll
                for (int j = 0; j < 8; j++) fma2(acc[i][j], a2[i], w2[j]);
        }
        __syncthreads();
    }

#pragma unroll
    for (int i = 0; i < 4; i++) {
        int m = m0 + tm + 16 * i;
        if (m >= M) continue;
#pragma unroll
        for (int j = 0; j < 8; j++) {
            int n = n0 + tn + 16 * j;
            if (n >= N) continue;
            float v = pairsum(acc[i][j]);
            if (bias0) v += bias0[n];
            if (bias1) v += bias1[n];
            C[(long)m * ldc + n] = v;
        }
    }
}

// ---------------- small-M GEMM (M=64 fixed), k-split partials ----------------
// grid = (N/32, KS); block 256; each block: 64 x 32 x Kps -> P[z][64][N]
__global__ __launch_bounds__(256) void gemm_small64(
    const float* __restrict__ A, int lda,
    const float* __restrict__ W, int ldw,
    float* __restrict__ P, int N, int Kps)
{
    __shared__ float As[64][34];
    __shared__ float Ws[32][34];
    const int tid  = threadIdx.x;
    const int n0   = blockIdx.x * 32;
    const int kb   = blockIdx.y * Kps;
    const int tm   = tid >> 4;
    const int tn   = tid & 15;
    const int lrow = tid >> 3;
    const int lcol = (tid & 7) << 2;

    u64 acc[4][2];
#pragma unroll
    for (int i = 0; i < 4; i++) { acc[i][0] = 0ull; acc[i][1] = 0ull; }

    const int nk = Kps >> 5;
    float4 pa0, pa1, pw;
    {
        int k = kb + lcol;
        pa0 = *reinterpret_cast<const float4*>(A + (long)lrow * lda + k);
        pa1 = *reinterpret_cast<const float4*>(A + (long)(lrow + 32) * lda + k);
        pw  = *reinterpret_cast<const float4*>(W + (long)(n0 + lrow) * ldw + k);
    }
    for (int c = 0; c < nk; c++) {
        sts4(&As[lrow][lcol],      pa0);
        sts4(&As[lrow + 32][lcol], pa1);
        sts4(&Ws[lrow][lcol],      pw);
        __syncthreads();
        if (c + 1 < nk) {
            int k = kb + ((c + 1) << 5) + lcol;
            pa0 = *reinterpret_cast<const float4*>(A + (long)lrow * lda + k);
            pa1 = *reinterpret_cast<const float4*>(A + (long)(lrow + 32) * lda + k);
            pw  = *reinterpret_cast<const float4*>(W + (long)(n0 + lrow) * ldw + k);
        }
#pragma unroll
        for (int kk = 0; kk < 16; kk++) {
            u64 a2[4], w2[2];
#pragma unroll
            for (int i = 0; i < 4; i++)
                a2[i] = *reinterpret_cast<const u64*>(&As[tm + 16 * i][kk << 1]);
#pragma unroll
            for (int j = 0; j < 2; j++)
                w2[j] = *reinterpret_cast<const u64*>(&Ws[tn + 16 * j][kk << 1]);
#pragma unroll
            for (int i = 0; i < 4; i++)
#pragma unroll
                for (int j = 0; j < 2; j++) fma2(acc[i][j], a2[i], w2[j]);
        }
        __syncthreads();
    }

    float* out = P + (long)blockIdx.y * 64 * N;
#pragma unroll
    for (int i = 0; i < 4; i++)
#pragma unroll
        for (int j = 0; j < 2; j++)
            out[(tm + 16 * i) * (long)N + n0 + tn + 16 * j] = pairsum(acc[i][j]);
}

// ---------------- LSTM gate fusion: G = P[0]+P[1]+D1(+D2); update c, write h ----------------
__global__ void lstm_gates(const float* __restrict__ P,          // [2][64][2048]
                           const float* __restrict__ D1, int ldd1,
                           const float* __restrict__ D2,         // ld 2048 or null
                           float* __restrict__ c,                // [64][512]
                           float* __restrict__ h_out, int h_stride)
{
    int idx = blockIdx.x * blockDim.x + threadIdx.x;  // 0..32767
    int b = idx >> 9, u = idx & 511;
    const float* g0 = P + (long)b * G4;
    const float* g1 = P + (long)CB * G4 + (long)b * G4;
    const float* d1 = D1 + (long)b * ldd1;
    float gi = g0[u]        + g1[u]        + d1[u];
    float gf = g0[512 + u]  + g1[512 + u]  + d1[512 + u];
    float gg = g0[1024 + u] + g1[1024 + u] + d1[1024 + u];
    float go = g0[1536 + u] + g1[1536 + u] + d1[1536 + u];
    if (D2) {
        const float* d2 = D2 + (long)b * G4;
        gi += d2[u]; gf += d2[512 + u]; gg += d2[1024 + u]; go += d2[1536 + u];
    }
    float i_ = 1.f / (1.f + expf(-gi));
    float f_ = 1.f / (1.f + expf(-gf));
    float g_ = tanhf(gg);
    float o_ = 1.f / (1.f + expf(-go));
    float cn = f_ * c[idx] + i_ * g_;
    c[idx] = cn;
    h_out[(long)b * h_stride + u] = o_ * tanhf(cn);
}

// ---------------- small elementwise kernels ----------------
__global__ void zero_state(float* cF, float* cB, float* cD, float* hz)
{
    int idx = blockIdx.x * blockDim.x + threadIdx.x;  // 32768
    cF[idx] = 0.f; cB[idx] = 0.f; cD[idx] = 0.f; hz[idx] = 0.f;
}

__global__ void ctx_sum(const float* __restrict__ hF, const float* __restrict__ hB,
                        float* __restrict__ ctx)
{
    int idx = blockIdx.x * blockDim.x + threadIdx.x;  // 64*1024
    int b = idx >> 10, j = idx & 1023;
    float s = 0.f;
    if (j < 512) {
        for (int l = 0; l < CL; l++) s += hF[((long)l * CB + b) * CH + j];
    } else {
        int j2 = j - 512;
        for (int l = 0; l < CL; l++) s += hB[((long)l * CB + b) * CH + j2];
    }
    ctx[idx] = s;
}

__global__ void ctx_combine(const float* __restrict__ P,   // [4][64][2048]
                            const float* __restrict__ b0,
                            const float* __restrict__ b1,
                            float* __restrict__ ctxW)
{
    int idx = blockIdx.x * blockDim.x + threadIdx.x;  // 64*2048
    int b = idx >> 11, n = idx & 2047;
    float s = b0[n] + b1[n];
#pragma unroll
    for (int z = 0; z < 4; z++) s += P[((long)z * CB + b) * G4 + n];
    ctxW[idx] = s;
}

__global__ void gather_emb(const float* __restrict__ emb, const int* __restrict__ targets,
                           float* __restrict__ dst)
{
    int idx = blockIdx.x * blockDim.x + threadIdx.x;  // 39*64*512
    int e = idx & 511;
    int r = idx >> 9;          // r = t*B + b
    int t = r / CB, b = r - t * CB;
    int tgt = targets[b * CL + t];
    dst[idx] = emb[(long)tgt * CE + e];
}

// ---------------- launch ----------------
extern "C" void kernel_launch(void* const* d_in, const int* in_sizes, int n_in,
                              void* d_out, int out_size)
{
    (void)in_sizes; (void)n_in; (void)out_size;
    const float* feats  = (const float*)d_in[0];
    const float* feat_W = (const float*)d_in[1];
    const float* feat_b = (const float*)d_in[2];
    const float* Wih_f  = (const float*)d_in[3];
    const float* Whh_f  = (const float*)d_in[4];
    const float* bih_f  = (const float*)d_in[5];
    const float* bhh_f  = (const float*)d_in[6];
    const float* Wih_b  = (const float*)d_in[7];
    const float* Whh_b  = (const float*)d_in[8];
    const float* bih_b  = (const float*)d_in[9];
    const float* bhh_b  = (const float*)d_in[10];
    const float* emb    = (const float*)d_in[11];
    const float* Wih_d  = (const float*)d_in[12];
    const float* Whh_d  = (const float*)d_in[13];
    const float* bih_d  = (const float*)d_in[14];
    const float* bhh_d  = (const float*)d_in[15];
    // d_in[16..20]: attention params — provably unused (softmax over singleton axis -> ones)
    const float* out_W  = (const float*)d_in[21];
    const float* out_b  = (const float*)d_in[22];
    const int*   targets = (const int*)d_in[23];
    float* out = (float*)d_out;

    float* S = nullptr;
    cudaGetSymbolAddress((void**)&S, g_scratch);
    float* x     = S + OFF_X;
    float* ginF  = S + OFF_GINF;
    float* ginB  = S + OFF_GINB;
    float* hF    = S + OFF_HF;
    float* hB    = S + OFF_HB;
    float* hD    = S + OFF_HD;
    float* cF    = S + OFF_CF;
    float* cBb   = S + OFF_CB2;
    float* cD    = S + OFF_CD;
    float* hz    = S + OFF_HZ;
    float* ctx   = S + OFF_CTX;
    float* demb  = S + OFF_DEMB;
    float* embW  = S + OFF_EMBW;
    float* ctxW  = S + OFF_CTXW;
    float* part  = S + OFF_PART;

    zero_state<<<128, 256>>>(cF, cBb, cD, hz);

    // x = feats @ feat_W^T + feat_b         [2560,2048] x [512,2048]^T
    gemm_big<<<dim3(40, 4), 256>>>(feats, CDF, feat_W, CDF, x, CH, CB * CL, CH, CDF, feat_b, nullptr);
    // input-gate precompute for both LSTMs (biases folded)
    gemm_big<<<dim3(40, 16), 256>>>(x, CH, Wih_f, CH, ginF, G4, CB * CL, G4, CH, bih_f, bhh_f);
    gemm_big<<<dim3(40, 16), 256>>>(x, CH, Wih_b, CH, ginB, G4, CB * CL, G4, CH, bih_b, bhh_b);

    // forward LSTM
    for (int l = 0; l < CL; l++) {
        const float* hp = (l == 0) ? hz : hF + (long)(l - 1) * CB * CH;
        gemm_small64<<<dim3(64, 2), 256>>>(hp, CH, Whh_f, CH, part, G4, 256);
        lstm_gates<<<128, 256>>>(part, ginF + (long)l * G4, CL * G4, nullptr, cF,
                                 hF + (long)l * CB * CH, CH);
    }
    // backward LSTM
    for (int l = CL - 1; l >= 0; l--) {
        const float* hp = (l == CL - 1) ? hz : hB + (long)(l + 1) * CB * CH;
        gemm_small64<<<dim3(64, 2), 256>>>(hp, CH, Whh_b, CH, part, G4, 256);
        lstm_gates<<<128, 256>>>(part, ginB + (long)l * G4, CL * G4, nullptr, cBb,
                                 hB + (long)l * CB * CH, CH);
    }

    // ctx[b] = sum_l enc[b,l,:]   (attention collapses to this)
    ctx_sum<<<256, 256>>>(hF, hB, ctx);

    // decoder input-gate precompute
    gather_emb<<<(CT * CB * CE) / 256, 256>>>(emb, targets, demb);
    gemm_big<<<dim3(39, 16), 256>>>(demb, CE, Wih_d, 2 * CH + CE, embW, G4, CT * CB, G4, CE,
                                    nullptr, nullptr);
    gemm_small64<<<dim3(64, 4), 256>>>(ctx, 2 * CH, Wih_d + CE, 2 * CH + CE, part, G4, 256);
    ctx_combine<<<512, 256>>>(part, bih_d, bhh_d, ctxW);

    // decoder LSTM (hD layout [B][T][H] so the final GEMM maps straight to out[b,t,v])
    for (int t = 0; t < CT; t++) {
        const float* hp; int lda;
        if (t == 0) { hp = hz; lda = CH; }
        else        { hp = hD + (long)(t - 1) * CH; lda = CT * CH; }
        gemm_small64<<<dim3(64, 2), 256>>>(hp, lda, Whh_d, CH, part, G4, 256);
        lstm_gates<<<128, 256>>>(part, embW + (long)t * CB * G4, G4, ctxW, cD,
                                 hD + (long)t * CH, CT * CH);
    }

    // output projection: out[b,t,:] = hD[b,t,:] @ out_W^T + out_b
    gemm_big<<<dim3(39, 157), 256>>>(hD, CH, out_W, CH, out, CV, CT * CB, CV, CH, out_b, nullptr);
}